// round 1
// baseline (speedup 1.0000x reference)
#include <cuda_runtime.h>
#include <cuda_bf16.h>
#include <math.h>

// ---------------------------------------------------------------------------
// Problem constants
//   B=2, in spatial 16x16 -> expanded 32x32 (L=1024, S=B*L=2048)
//   out_dim=384, Di=768, N=16, R=48, K=4 directions, G=8 groups, depth=2
// ---------------------------------------------------------------------------

#define S_TOT 2048          // B * 32 * 32
#define L_LEN 1024
#define DI    768
#define DOUT  384
#define NST   16
#define CT    80            // R + 2N
#define RLOW  48

// ------------------------- scratch (static device mem) ---------------------
__device__ float g_xT  [2 * 256 * 768];
__device__ float g_pe  [512 * 1536];
__device__ float g_cat [S_TOT * 768];
__device__ float g_xh  [S_TOT * DOUT];
__device__ float g_h   [S_TOT * DOUT];
__device__ float g_xz  [S_TOT * 1536];
__device__ float g_xc  [S_TOT * DI];
__device__ float g_xdbl[8 * L_LEN * CT];
__device__ float g_dts [8 * L_LEN * DI];
__device__ float g_ys  [8 * L_LEN * DI];
__device__ float g_y   [S_TOT * DI];
__device__ int   g_rowmap[8 * L_LEN];

// ------------------------- helpers ------------------------------------------
__device__ __forceinline__ float block_reduce_sum(float v, float* red) {
#pragma unroll
    for (int o = 16; o > 0; o >>= 1) v += __shfl_xor_sync(0xffffffffu, v, o);
    int warp = threadIdx.x >> 5;
    if ((threadIdx.x & 31) == 0) red[warp] = v;
    __syncthreads();
    int nw = blockDim.x >> 5;
    float s = 0.f;
    for (int i = 0; i < nw; i++) s += red[i];
    __syncthreads();
    return s;
}

__device__ __forceinline__ int swap_l(int l) { return ((l & 31) << 5) | (l >> 5); }

// ------------------------- generic tiled SGEMM  (C = A * W^T) ---------------
// A: (M x Kdim) rows via optional rowmap. W: (Ncols x Kdim). C: (M x Ncols).
// flags: 1 = add bias[col], 2 = softplus, 4 = accumulate into C.
__global__ void gemm_tn(const float* __restrict__ A, const float* __restrict__ W,
                        const float* __restrict__ bias, float* __restrict__ C,
                        int M, int Ncols, int Kdim, int lda, int ldw, int ldc,
                        long aBatch, long wBatch, int wMod, long biasBatch, long cBatch,
                        const int* __restrict__ rowmap, int rmBatch, int flags)
{
    const int BK = 8;
    __shared__ float As[BK][132];
    __shared__ float Wsh[BK][132];

    int z = blockIdx.z;
    int wz = (wMod > 1) ? (z % wMod) : 0;
    const float* Ab = A + (long)z * aBatch;
    const float* Wb = W + (long)wz * wBatch;
    const float* biasb = bias ? (bias + (long)wz * biasBatch) : (const float*)0;
    float* Cb = C + (long)z * cBatch;
    const int* rm = rowmap ? (rowmap + (long)z * rmBatch) : (const int*)0;

    int m0 = blockIdx.y * 128, n0 = blockIdx.x * 128;
    int tid = threadIdx.x;
    int ty = tid >> 4, tx = tid & 15;

    float acc[8][8];
#pragma unroll
    for (int i = 0; i < 8; i++)
#pragma unroll
        for (int j = 0; j < 8; j++) acc[i][j] = 0.f;

    int lr = tid >> 1;
    int lk = (tid & 1) * 4;
    int arow_l = m0 + lr;
    int arow = rm ? rm[arow_l] : arow_l;
    int wrow = n0 + lr;
    bool wok = wrow < Ncols;
    const float* aptr = Ab + (long)arow * lda + lk;
    const float* wptr = wok ? (Wb + (long)wrow * ldw + lk) : Wb;

    for (int k0 = 0; k0 < Kdim; k0 += BK) {
        float4 av = *(const float4*)(aptr + k0);
        float4 wv = wok ? *(const float4*)(wptr + k0) : make_float4(0.f, 0.f, 0.f, 0.f);
        __syncthreads();
        As[lk + 0][lr] = av.x; As[lk + 1][lr] = av.y; As[lk + 2][lr] = av.z; As[lk + 3][lr] = av.w;
        Wsh[lk + 0][lr] = wv.x; Wsh[lk + 1][lr] = wv.y; Wsh[lk + 2][lr] = wv.z; Wsh[lk + 3][lr] = wv.w;
        __syncthreads();
#pragma unroll
        for (int kk = 0; kk < BK; kk++) {
            float a[8], w[8];
            float4 a0 = *(const float4*)&As[kk][ty * 8];
            float4 a1 = *(const float4*)&As[kk][ty * 8 + 4];
            float4 w0 = *(const float4*)&Wsh[kk][tx * 8];
            float4 w1 = *(const float4*)&Wsh[kk][tx * 8 + 4];
            a[0]=a0.x;a[1]=a0.y;a[2]=a0.z;a[3]=a0.w;a[4]=a1.x;a[5]=a1.y;a[6]=a1.z;a[7]=a1.w;
            w[0]=w0.x;w[1]=w0.y;w[2]=w0.z;w[3]=w0.w;w[4]=w1.x;w[5]=w1.y;w[6]=w1.z;w[7]=w1.w;
#pragma unroll
            for (int i = 0; i < 8; i++)
#pragma unroll
                for (int j = 0; j < 8; j++) acc[i][j] = fmaf(a[i], w[j], acc[i][j]);
        }
    }

#pragma unroll
    for (int i = 0; i < 8; i++) {
        int row = m0 + ty * 8 + i;
#pragma unroll
        for (int j = 0; j < 8; j++) {
            int col = n0 + tx * 8 + j;
            if (col < Ncols) {
                float v = acc[i][j];
                if (flags & 1) v += biasb[col];
                if (flags & 2) v = (v > 20.f) ? v : log1pf(expf(v));
                long cidx = (long)row * ldc + col;
                if (flags & 4) v += Cb[cidx];
                Cb[cidx] = v;
            }
        }
    }
}

// ------------------------- transpose (per-batch rows x cols -> cols x rows) -
__global__ void transpose_kernel(const float* __restrict__ src, float* __restrict__ dst,
                                 int rows, int cols)
{
    __shared__ float tile[32][33];
    int c0 = blockIdx.x * 32, r0 = blockIdx.y * 32, bz = blockIdx.z;
    const float* s = src + (long)bz * rows * cols;
    float* d = dst + (long)bz * rows * cols;
    for (int i = threadIdx.y; i < 32; i += 8)
        tile[i][threadIdx.x] = s[(long)(r0 + i) * cols + c0 + threadIdx.x];
    __syncthreads();
    for (int i = threadIdx.y; i < 32; i += 8)
        d[(long)(c0 + i) * rows + r0 + threadIdx.x] = tile[threadIdx.x][i];
}

// ------------------------- rowmap init --------------------------------------
__global__ void rowmap_init()
{
    int g = blockIdx.x, l = threadIdx.x;
    int k = g & 3, b = g >> 2;
    int s;
    if (k == 0) s = l;
    else if (k == 1) s = swap_l(l);
    else if (k == 2) s = 1023 - l;
    else { int m = 1023 - l; s = swap_l(m); }
    g_rowmap[g * L_LEN + l] = b * L_LEN + s;
}

// ------------------------- patch-expand LN + concat skip --------------------
__global__ void pe_cat_kernel(const float* __restrict__ pe, const float* __restrict__ skip,
                              const float* __restrict__ nw, const float* __restrict__ nb,
                              float* __restrict__ cat)
{
    int pix = blockIdx.x;                    // b*1024 + Y*32 + X
    int b = pix >> 10, Y = (pix >> 5) & 31, X = pix & 31;
    int h = Y >> 1, p = Y & 1, w = X >> 1, q = X & 1;
    const float* src = pe + (long)(b * 256 + h * 16 + w) * 1536 + (p * 2 + q) * 384;

    __shared__ float red[32];
    float v[3]; float ssum = 0.f;
#pragma unroll
    for (int j = 0; j < 3; j++) { v[j] = src[threadIdx.x + j * 128]; ssum += v[j]; }
    float mean = block_reduce_sum(ssum, red) * (1.f / 384.f);
    float vs = 0.f;
#pragma unroll
    for (int j = 0; j < 3; j++) { float d = v[j] - mean; vs += d * d; }
    float var = block_reduce_sum(vs, red) * (1.f / 384.f);
    float rstd = rsqrtf(var + 1e-5f);

    float* dst = cat + (long)pix * 768;
#pragma unroll
    for (int j = 0; j < 3; j++) {
        int c = threadIdx.x + j * 128;
        dst[c] = (v[j] - mean) * rstd * nw[c] + nb[c];
    }
    const float* sp = skip + (long)b * 384 * 1024 + (Y * 32 + X);
#pragma unroll
    for (int j = 0; j < 3; j++) {
        int c = threadIdx.x + j * 128;
        dst[384 + c] = sp[(long)c * 1024];
    }
}

// ------------------------- LN over 384 ---------------------------------------
__global__ void ln384_kernel(const float* __restrict__ in, float* __restrict__ out,
                             const float* __restrict__ w, const float* __restrict__ b)
{
    int row = blockIdx.x;
    const float* src = in + (long)row * 384;
    __shared__ float red[32];
    float v[3]; float ssum = 0.f;
#pragma unroll
    for (int j = 0; j < 3; j++) { v[j] = src[threadIdx.x + j * 128]; ssum += v[j]; }
    float mean = block_reduce_sum(ssum, red) * (1.f / 384.f);
    float vs = 0.f;
#pragma unroll
    for (int j = 0; j < 3; j++) { float d = v[j] - mean; vs += d * d; }
    float var = block_reduce_sum(vs, red) * (1.f / 384.f);
    float rstd = rsqrtf(var + 1e-5f);
    float* dst = out + (long)row * 384;
#pragma unroll
    for (int j = 0; j < 3; j++) {
        int c = threadIdx.x + j * 128;
        dst[c] = (v[j] - mean) * rstd * w[c] + b[c];
    }
}

// ------------------------- depthwise 3x3 conv + bias + silu ------------------
__global__ void conv_kernel(const float* __restrict__ xz, const float* __restrict__ cw,
                            const float* __restrict__ cb, float* __restrict__ xc)
{
    int pix = blockIdx.x;
    int b = pix >> 10, Y = (pix >> 5) & 31, X = pix & 31;
    int t = threadIdx.x;
    float acc[3] = {0.f, 0.f, 0.f};
    for (int dy = -1; dy <= 1; dy++) {
        int yy = Y + dy; if ((unsigned)yy >= 32u) continue;
        for (int dx = -1; dx <= 1; dx++) {
            int xx = X + dx; if ((unsigned)xx >= 32u) continue;
            const float* row = xz + (long)(b * 1024 + yy * 32 + xx) * 1536;
            int widx = (dy + 1) * 3 + (dx + 1);
#pragma unroll
            for (int j = 0; j < 3; j++) {
                int c = t + j * 256;
                acc[j] = fmaf(row[c], cw[c * 9 + widx], acc[j]);
            }
        }
    }
    float* dst = xc + (long)pix * 768;
#pragma unroll
    for (int j = 0; j < 3; j++) {
        int c = t + j * 256;
        float v = acc[j] + cb[c];
        dst[c] = v / (1.f + expf(-v));
    }
}

// ------------------------- selective scan -----------------------------------
// one thread per (g, d) lane; 16 states in registers.
__global__ void scan_kernel(const float* __restrict__ dts, const float* __restrict__ xc,
                            const float* __restrict__ xdbl, const float* __restrict__ A_log,
                            const float* __restrict__ Ds, float* __restrict__ ys)
{
    int g = blockIdx.x;
    int d = blockIdx.y * blockDim.x + threadIdx.x;
    int k = g & 3, b = g >> 2;

    float A[NST], h[NST];
    const float* al = A_log + ((long)k * DI + d) * NST;
#pragma unroll
    for (int n = 0; n < NST; n++) { A[n] = -expf(al[n]); h[n] = 0.f; }
    float Dv = Ds[k * DI + d];

    const float* dtp = dts + (long)g * L_LEN * DI + d;
    const float* xdp = xdbl + (long)g * L_LEN * CT;
    long xcb = (long)b * L_LEN * DI + d;
    float* yp = ys + (long)g * L_LEN * DI + d;

    for (int l = 0; l < L_LEN; l++) {
        int s;
        if (k == 0) s = l;
        else if (k == 1) s = swap_l(l);
        else if (k == 2) s = 1023 - l;
        else { int m = 1023 - l; s = swap_l(m); }

        float dt = dtp[(long)l * DI];
        float u  = xc[xcb + (long)s * DI];
        float dtu = dt * u;
        const float* bc = xdp + l * CT;
        float y = Dv * u;
#pragma unroll
        for (int n = 0; n < NST; n++) {
            float e = expf(dt * A[n]);
            h[n] = fmaf(e, h[n], dtu * bc[RLOW + n]);
            y = fmaf(h[n], bc[RLOW + NST + n], y);
        }
        yp[(long)l * DI] = y;
    }
}

// ------------------------- combine 4 dirs + out-LN + silu(z) gate ------------
__global__ void combine_kernel(const float* __restrict__ ys, const float* __restrict__ xz,
                               const float* __restrict__ onw, const float* __restrict__ onb,
                               float* __restrict__ yout)
{
    int bs = blockIdx.x;                 // b*1024 + s
    int b = bs >> 10, s = bs & 1023;
    int sw = swap_l(s);
    long base0 = ((long)(b * 4 + 0) * L_LEN + s)          * DI;
    long base1 = ((long)(b * 4 + 1) * L_LEN + sw)         * DI;
    long base2 = ((long)(b * 4 + 2) * L_LEN + (1023 - s)) * DI;
    long base3 = ((long)(b * 4 + 3) * L_LEN + (1023 - sw))* DI;

    __shared__ float red[32];
    float v[3]; float ssum = 0.f;
#pragma unroll
    for (int j = 0; j < 3; j++) {
        int c = threadIdx.x + j * 256;
        v[j] = ys[base0 + c] + ys[base1 + c] + ys[base2 + c] + ys[base3 + c];
        ssum += v[j];
    }
    float mean = block_reduce_sum(ssum, red) * (1.f / 768.f);
    float vs = 0.f;
#pragma unroll
    for (int j = 0; j < 3; j++) { float d = v[j] - mean; vs += d * d; }
    float var = block_reduce_sum(vs, red) * (1.f / 768.f);
    float rstd = rsqrtf(var + 1e-5f);

#pragma unroll
    for (int j = 0; j < 3; j++) {
        int c = threadIdx.x + j * 256;
        float zz = xz[(long)bs * 1536 + 768 + c];
        float sil = zz / (1.f + expf(-zz));
        yout[(long)bs * DI + c] = ((v[j] - mean) * rstd * onw[c] + onb[c]) * sil;
    }
}

// ---------------------------------------------------------------------------
extern "C" void kernel_launch(void* const* d_in, const int* in_sizes, int n_in,
                              void* d_out, int out_size)
{
    const float* x      = (const float*)d_in[0];
    const float* skip   = (const float*)d_in[1];
    const float* pe_w   = (const float*)d_in[2];
    const float* pe_nw  = (const float*)d_in[3];
    const float* pe_nb  = (const float*)d_in[4];
    const float* lp_w   = (const float*)d_in[5];
    const float* lp_b   = (const float*)d_in[6];
    const float* bln_w  = (const float*)d_in[7];
    const float* bln_b  = (const float*)d_in[8];
    const float* in_w   = (const float*)d_in[9];
    const float* conv_w = (const float*)d_in[10];
    const float* conv_b = (const float*)d_in[11];
    const float* xp_w   = (const float*)d_in[12];
    const float* dt_w   = (const float*)d_in[13];
    const float* dt_b   = (const float*)d_in[14];
    const float* A_log  = (const float*)d_in[15];
    const float* Ds     = (const float*)d_in[16];
    const float* on_w   = (const float*)d_in[17];
    const float* on_b   = (const float*)d_in[18];
    const float* out_w  = (const float*)d_in[19];
    float* out = (float*)d_out;

    float *xT, *pe, *cat, *xh, *hbuf, *xz, *xc, *xdbl, *dts, *ys, *ybuf;
    int* rowmap;
    cudaGetSymbolAddress((void**)&xT,   g_xT);
    cudaGetSymbolAddress((void**)&pe,   g_pe);
    cudaGetSymbolAddress((void**)&cat,  g_cat);
    cudaGetSymbolAddress((void**)&xh,   g_xh);
    cudaGetSymbolAddress((void**)&hbuf, g_h);
    cudaGetSymbolAddress((void**)&xz,   g_xz);
    cudaGetSymbolAddress((void**)&xc,   g_xc);
    cudaGetSymbolAddress((void**)&xdbl, g_xdbl);
    cudaGetSymbolAddress((void**)&dts,  g_dts);
    cudaGetSymbolAddress((void**)&ys,   g_ys);
    cudaGetSymbolAddress((void**)&ybuf, g_y);
    cudaGetSymbolAddress((void**)&rowmap, g_rowmap);

    // x (B,768,16,16) -> xT (B,256,768)
    transpose_kernel<<<dim3(256 / 32, 768 / 32, 2), dim3(32, 8)>>>(x, xT, 768, 256);
    rowmap_init<<<8, 1024>>>();

    // patch-expand GEMM: (512 x 1536 x 768)
    gemm_tn<<<dim3(12, 4, 1), 256>>>(xT, pe_w, nullptr, pe, 512, 1536, 768,
                                     768, 768, 1536, 0, 0, 1, 0, 0, nullptr, 0, 0);
    // expand-reshape + LN + concat skip -> cat (2048 x 768)
    pe_cat_kernel<<<2048, 128>>>(pe, skip, pe_nw, pe_nb, cat);
    // linear proj: (2048 x 384 x 768) + bias -> xh
    gemm_tn<<<dim3(3, 16, 1), 256>>>(cat, lp_w, lp_b, xh, 2048, 384, 768,
                                     768, 768, 384, 0, 0, 1, 0, 0, nullptr, 0, 1);

    for (int layer = 0; layer < 2; layer++) {
        ln384_kernel<<<2048, 128>>>(xh, hbuf, bln_w + layer * 384, bln_b + layer * 384);
        // in_proj: (2048 x 1536 x 384)
        gemm_tn<<<dim3(12, 16, 1), 256>>>(hbuf, in_w + (long)layer * 1536 * 384, nullptr, xz,
                                          2048, 1536, 384, 384, 384, 1536,
                                          0, 0, 1, 0, 0, nullptr, 0, 0);
        // depthwise conv + silu -> xc (NHWC)
        conv_kernel<<<2048, 256>>>(xz, conv_w + (long)layer * 768 * 9,
                                   conv_b + layer * 768, xc);
        // x_proj: 8 x (1024 x 80 x 768) with direction row-permutation
        gemm_tn<<<dim3(1, 8, 8), 256>>>(xc, xp_w + (long)layer * 4 * 80 * 768, nullptr, xdbl,
                                        1024, 80, 768, 768, 768, 80,
                                        0, (long)80 * 768, 4, 0, (long)1024 * 80,
                                        rowmap, 1024, 0);
        // dt_proj: 8 x (1024 x 768 x 48) + bias + softplus
        gemm_tn<<<dim3(6, 8, 8), 256>>>(xdbl, dt_w + (long)layer * 4 * 768 * 48,
                                        dt_b + (long)layer * 4 * 768, dts,
                                        1024, 768, 48, 80, 48, 768,
                                        (long)1024 * 80, (long)768 * 48, 4, 768,
                                        (long)1024 * 768, nullptr, 0, 1 | 2);
        // selective scan
        scan_kernel<<<dim3(8, 6), 128>>>(dts, xc, xdbl,
                                         A_log + (long)layer * 4 * 768 * 16,
                                         Ds + (long)layer * 4 * 768, ys);
        // merge directions + out-LN + silu(z) gate
        combine_kernel<<<2048, 256>>>(ys, xz, on_w + layer * 768, on_b + layer * 768, ybuf);
        // out_proj + residual: (2048 x 384 x 768), accumulate into xh
        gemm_tn<<<dim3(3, 16, 1), 256>>>(ybuf, out_w + (long)layer * 384 * 768, nullptr, xh,
                                         2048, 384, 768, 768, 768, 384,
                                         0, 0, 1, 0, 0, nullptr, 0, 4);
    }

    // xh (B,1024,384) -> out (B,384,32,32)
    transpose_kernel<<<dim3(384 / 32, 1024 / 32, 2), dim3(32, 8)>>>(xh, out, 1024, 384);
}

// round 2
// speedup vs baseline: 1.7960x; 1.7960x over previous
#include <cuda_runtime.h>
#include <cuda_bf16.h>
#include <math.h>

// ---------------------------------------------------------------------------
// Problem constants
//   B=2, in spatial 16x16 -> expanded 32x32 (L=1024, S=B*L=2048)
//   out_dim=384, Di=768, N=16, R=48, K=4 directions, G=8 groups, depth=2
// ---------------------------------------------------------------------------

#define S_TOT 2048          // B * 32 * 32
#define L_LEN 1024
#define DI    768
#define DOUT  384
#define NST   16
#define CT    80            // R + 2N
#define RLOW  48

// ------------------------- scratch (static device mem) ---------------------
__device__ float g_xT  [2 * 256 * 768];
__device__ float g_pe  [512 * 1536];
__device__ float g_cat [S_TOT * 768];
__device__ float g_xh  [S_TOT * DOUT];
__device__ float g_h   [S_TOT * DOUT];
__device__ float g_xz  [S_TOT * 1536];
__device__ float g_xc  [S_TOT * DI];
__device__ float g_xdbl[8 * L_LEN * CT];
__device__ float g_dts [8 * L_LEN * DI];
__device__ float g_ys  [8 * L_LEN * DI];
__device__ float g_y   [S_TOT * DI];
__device__ int   g_rowmap[8 * L_LEN];

// ------------------------- helpers ------------------------------------------
__device__ __forceinline__ float block_reduce_sum(float v, float* red) {
#pragma unroll
    for (int o = 16; o > 0; o >>= 1) v += __shfl_xor_sync(0xffffffffu, v, o);
    int warp = threadIdx.x >> 5;
    if ((threadIdx.x & 31) == 0) red[warp] = v;
    __syncthreads();
    int nw = blockDim.x >> 5;
    float s = 0.f;
    for (int i = 0; i < nw; i++) s += red[i];
    __syncthreads();
    return s;
}

__device__ __forceinline__ int swap_l(int l) { return ((l & 31) << 5) | (l >> 5); }

__device__ __forceinline__ float silu_f(float v) { return v / (1.f + __expf(-v)); }

// ------------------------- generic tiled SGEMM  (C = A * W^T) ---------------
// A: (M x Kdim) rows via optional rowmap. W: (Ncols x Kdim). C: (M x Ncols).
// flags: 1 = add bias[col], 2 = softplus, 4 = accumulate into C.
// Software-pipelined: next k-tile is fetched into registers while the current
// tile is being consumed from shared memory.
__global__ void gemm_tn(const float* __restrict__ A, const float* __restrict__ W,
                        const float* __restrict__ bias, float* __restrict__ C,
                        int M, int Ncols, int Kdim, int lda, int ldw, int ldc,
                        long aBatch, long wBatch, int wMod, long biasBatch, long cBatch,
                        const int* __restrict__ rowmap, int rmBatch, int flags)
{
    const int BK = 8;
    __shared__ float As[BK][132];
    __shared__ float Wsh[BK][132];

    int z = blockIdx.z;
    int wz = (wMod > 1) ? (z % wMod) : 0;
    const float* Ab = A + (long)z * aBatch;
    const float* Wb = W + (long)wz * wBatch;
    const float* biasb = bias ? (bias + (long)wz * biasBatch) : (const float*)0;
    float* Cb = C + (long)z * cBatch;
    const int* rm = rowmap ? (rowmap + (long)z * rmBatch) : (const int*)0;

    int m0 = blockIdx.y * 128, n0 = blockIdx.x * 128;
    int tid = threadIdx.x;
    int ty = tid >> 4, tx = tid & 15;

    float acc[8][8];
#pragma unroll
    for (int i = 0; i < 8; i++)
#pragma unroll
        for (int j = 0; j < 8; j++) acc[i][j] = 0.f;

    int lr = tid >> 1;
    int lk = (tid & 1) * 4;
    int arow_l = m0 + lr;
    int arow = rm ? rm[arow_l] : arow_l;
    int wrow = n0 + lr;
    bool wok = wrow < Ncols;
    const float* aptr = Ab + (long)arow * lda + lk;
    const float* wptr = wok ? (Wb + (long)wrow * ldw + lk) : Wb;

    // prefetch first tile
    float4 av = *(const float4*)(aptr);
    float4 wv = wok ? *(const float4*)(wptr) : make_float4(0.f, 0.f, 0.f, 0.f);

    for (int k0 = 0; k0 < Kdim; k0 += BK) {
        __syncthreads();
        As[lk + 0][lr] = av.x; As[lk + 1][lr] = av.y; As[lk + 2][lr] = av.z; As[lk + 3][lr] = av.w;
        Wsh[lk + 0][lr] = wv.x; Wsh[lk + 1][lr] = wv.y; Wsh[lk + 2][lr] = wv.z; Wsh[lk + 3][lr] = wv.w;
        __syncthreads();
        if (k0 + BK < Kdim) {                      // prefetch next tile (overlaps compute)
            av = *(const float4*)(aptr + k0 + BK);
            wv = wok ? *(const float4*)(wptr + k0 + BK) : make_float4(0.f, 0.f, 0.f, 0.f);
        }
#pragma unroll
        for (int kk = 0; kk < BK; kk++) {
            float a[8], w[8];
            float4 a0 = *(const float4*)&As[kk][ty * 8];
            float4 a1 = *(const float4*)&As[kk][ty * 8 + 4];
            float4 w0 = *(const float4*)&Wsh[kk][tx * 8];
            float4 w1 = *(const float4*)&Wsh[kk][tx * 8 + 4];
            a[0]=a0.x;a[1]=a0.y;a[2]=a0.z;a[3]=a0.w;a[4]=a1.x;a[5]=a1.y;a[6]=a1.z;a[7]=a1.w;
            w[0]=w0.x;w[1]=w0.y;w[2]=w0.z;w[3]=w0.w;w[4]=w1.x;w[5]=w1.y;w[6]=w1.z;w[7]=w1.w;
#pragma unroll
            for (int i = 0; i < 8; i++)
#pragma unroll
                for (int j = 0; j < 8; j++) acc[i][j] = fmaf(a[i], w[j], acc[i][j]);
        }
    }

#pragma unroll
    for (int i = 0; i < 8; i++) {
        int row = m0 + ty * 8 + i;
#pragma unroll
        for (int j = 0; j < 8; j++) {
            int col = n0 + tx * 8 + j;
            if (col < Ncols) {
                float v = acc[i][j];
                if (flags & 1) v += biasb[col];
                if (flags & 2) v = (v > 20.f) ? v : log1pf(__expf(v));
                long cidx = (long)row * ldc + col;
                if (flags & 4) v += Cb[cidx];
                Cb[cidx] = v;
            }
        }
    }
}

// ------------------------- transpose (per-batch rows x cols -> cols x rows) -
__global__ void transpose_kernel(const float* __restrict__ src, float* __restrict__ dst,
                                 int rows, int cols)
{
    __shared__ float tile[32][33];
    int c0 = blockIdx.x * 32, r0 = blockIdx.y * 32, bz = blockIdx.z;
    const float* s = src + (long)bz * rows * cols;
    float* d = dst + (long)bz * rows * cols;
    for (int i = threadIdx.y; i < 32; i += 8)
        tile[i][threadIdx.x] = s[(long)(r0 + i) * cols + c0 + threadIdx.x];
    __syncthreads();
    for (int i = threadIdx.y; i < 32; i += 8)
        d[(long)(c0 + i) * rows + r0 + threadIdx.x] = tile[threadIdx.x][i];
}

// ------------------------- rowmap init --------------------------------------
__global__ void rowmap_init()
{
    int g = blockIdx.x, l = threadIdx.x;
    int k = g & 3, b = g >> 2;
    int s;
    if (k == 0) s = l;
    else if (k == 1) s = swap_l(l);
    else if (k == 2) s = 1023 - l;
    else { int m = 1023 - l; s = swap_l(m); }
    g_rowmap[g * L_LEN + l] = b * L_LEN + s;
}

// ------------------------- patch-expand LN + concat skip --------------------
__global__ void pe_cat_kernel(const float* __restrict__ pe, const float* __restrict__ skip,
                              const float* __restrict__ nw, const float* __restrict__ nb,
                              float* __restrict__ cat)
{
    int pix = blockIdx.x;                    // b*1024 + Y*32 + X
    int b = pix >> 10, Y = (pix >> 5) & 31, X = pix & 31;
    int h = Y >> 1, p = Y & 1, w = X >> 1, q = X & 1;
    const float* src = pe + (long)(b * 256 + h * 16 + w) * 1536 + (p * 2 + q) * 384;

    __shared__ float red[32];
    float v[3]; float ssum = 0.f;
#pragma unroll
    for (int j = 0; j < 3; j++) { v[j] = src[threadIdx.x + j * 128]; ssum += v[j]; }
    float mean = block_reduce_sum(ssum, red) * (1.f / 384.f);
    float vs = 0.f;
#pragma unroll
    for (int j = 0; j < 3; j++) { float d = v[j] - mean; vs += d * d; }
    float var = block_reduce_sum(vs, red) * (1.f / 384.f);
    float rstd = rsqrtf(var + 1e-5f);

    float* dst = cat + (long)pix * 768;
#pragma unroll
    for (int j = 0; j < 3; j++) {
        int c = threadIdx.x + j * 128;
        dst[c] = (v[j] - mean) * rstd * nw[c] + nb[c];
    }
    const float* sp = skip + (long)b * 384 * 1024 + (Y * 32 + X);
#pragma unroll
    for (int j = 0; j < 3; j++) {
        int c = threadIdx.x + j * 128;
        dst[384 + c] = sp[(long)c * 1024];
    }
}

// ------------------------- LN over 384 ---------------------------------------
__global__ void ln384_kernel(const float* __restrict__ in, float* __restrict__ out,
                             const float* __restrict__ w, const float* __restrict__ b)
{
    int row = blockIdx.x;
    const float* src = in + (long)row * 384;
    __shared__ float red[32];
    float v[3]; float ssum = 0.f;
#pragma unroll
    for (int j = 0; j < 3; j++) { v[j] = src[threadIdx.x + j * 128]; ssum += v[j]; }
    float mean = block_reduce_sum(ssum, red) * (1.f / 384.f);
    float vs = 0.f;
#pragma unroll
    for (int j = 0; j < 3; j++) { float d = v[j] - mean; vs += d * d; }
    float var = block_reduce_sum(vs, red) * (1.f / 384.f);
    float rstd = rsqrtf(var + 1e-5f);
    float* dst = out + (long)row * 384;
#pragma unroll
    for (int j = 0; j < 3; j++) {
        int c = threadIdx.x + j * 128;
        dst[c] = (v[j] - mean) * rstd * w[c] + b[c];
    }
}

// ------------------------- depthwise 3x3 conv + bias + silu ------------------
__global__ void conv_kernel(const float* __restrict__ xz, const float* __restrict__ cw,
                            const float* __restrict__ cb, float* __restrict__ xc)
{
    int pix = blockIdx.x;
    int b = pix >> 10, Y = (pix >> 5) & 31, X = pix & 31;
    int t = threadIdx.x;
    float acc[3] = {0.f, 0.f, 0.f};
    for (int dy = -1; dy <= 1; dy++) {
        int yy = Y + dy; if ((unsigned)yy >= 32u) continue;
        for (int dx = -1; dx <= 1; dx++) {
            int xx = X + dx; if ((unsigned)xx >= 32u) continue;
            const float* row = xz + (long)(b * 1024 + yy * 32 + xx) * 1536;
            int widx = (dy + 1) * 3 + (dx + 1);
#pragma unroll
            for (int j = 0; j < 3; j++) {
                int c = t + j * 256;
                acc[j] = fmaf(row[c], cw[c * 9 + widx], acc[j]);
            }
        }
    }
    float* dst = xc + (long)pix * 768;
#pragma unroll
    for (int j = 0; j < 3; j++) {
        int c = t + j * 256;
        float v = acc[j] + cb[c];
        dst[c] = silu_f(v);
    }
}

// ------------------------- selective scan -----------------------------------
// one thread per (g, d, n): 16 threads cooperate on one (g,d) lane, each
// owning a single state n. y is reduced across the 16-lane group via shfl.
// grid: (8 groups, 96 d-chunks), block: 128 threads (8 d-lanes x 16 states).
__global__ void scan_kernel(const float* __restrict__ dts, const float* __restrict__ xc,
                            const float* __restrict__ xdbl, const float* __restrict__ A_log,
                            const float* __restrict__ Ds, float* __restrict__ ys)
{
    int g = blockIdx.x;
    int k = g & 3, b = g >> 2;
    int tid = threadIdx.x;
    int n = tid & 15;
    int d = blockIdx.y * 8 + (tid >> 4);

    float A = -__expf(A_log[((long)(k * DI + d)) * NST + n]);
    float h = 0.f;
    float Dv = Ds[k * DI + d];

    const float* dtp = dts + (long)g * L_LEN * DI + d;
    const float* xdp = xdbl + (long)g * L_LEN * CT;
    const float* xcb = xc + (long)b * L_LEN * DI + d;
    float* yp = ys + (long)g * L_LEN * DI + d;

    for (int l = 0; l < L_LEN; l++) {
        int s;
        if (k == 0) s = l;
        else if (k == 1) s = swap_l(l);
        else if (k == 2) s = 1023 - l;
        else { int m = 1023 - l; s = swap_l(m); }

        float dt = dtp[(long)l * DI];          // broadcast within 16-lane group
        float u  = xcb[(long)s * DI];
        const float* bc = xdp + l * CT;
        float Bn = bc[RLOW + n];
        float Cn = bc[RLOW + NST + n];

        float e = __expf(dt * A);
        h = fmaf(e, h, dt * u * Bn);
        float t = h * Cn;
        t += __shfl_xor_sync(0xffffffffu, t, 1);
        t += __shfl_xor_sync(0xffffffffu, t, 2);
        t += __shfl_xor_sync(0xffffffffu, t, 4);
        t += __shfl_xor_sync(0xffffffffu, t, 8);
        if (n == 0) yp[(long)l * DI] = fmaf(Dv, u, t);
    }
}

// ------------------------- combine 4 dirs + out-LN + silu(z) gate ------------
__global__ void combine_kernel(const float* __restrict__ ys, const float* __restrict__ xz,
                               const float* __restrict__ onw, const float* __restrict__ onb,
                               float* __restrict__ yout)
{
    int bs = blockIdx.x;                 // b*1024 + s
    int b = bs >> 10, s = bs & 1023;
    int sw = swap_l(s);
    long base0 = ((long)(b * 4 + 0) * L_LEN + s)          * DI;
    long base1 = ((long)(b * 4 + 1) * L_LEN + sw)         * DI;
    long base2 = ((long)(b * 4 + 2) * L_LEN + (1023 - s)) * DI;
    long base3 = ((long)(b * 4 + 3) * L_LEN + (1023 - sw))* DI;

    __shared__ float red[32];
    float v[3]; float ssum = 0.f;
#pragma unroll
    for (int j = 0; j < 3; j++) {
        int c = threadIdx.x + j * 256;
        v[j] = ys[base0 + c] + ys[base1 + c] + ys[base2 + c] + ys[base3 + c];
        ssum += v[j];
    }
    float mean = block_reduce_sum(ssum, red) * (1.f / 768.f);
    float vs = 0.f;
#pragma unroll
    for (int j = 0; j < 3; j++) { float d = v[j] - mean; vs += d * d; }
    float var = block_reduce_sum(vs, red) * (1.f / 768.f);
    float rstd = rsqrtf(var + 1e-5f);

#pragma unroll
    for (int j = 0; j < 3; j++) {
        int c = threadIdx.x + j * 256;
        float zz = xz[(long)bs * 1536 + 768 + c];
        yout[(long)bs * DI + c] = ((v[j] - mean) * rstd * onw[c] + onb[c]) * silu_f(zz);
    }
}

// ---------------------------------------------------------------------------
extern "C" void kernel_launch(void* const* d_in, const int* in_sizes, int n_in,
                              void* d_out, int out_size)
{
    const float* x      = (const float*)d_in[0];
    const float* skip   = (const float*)d_in[1];
    const float* pe_w   = (const float*)d_in[2];
    const float* pe_nw  = (const float*)d_in[3];
    const float* pe_nb  = (const float*)d_in[4];
    const float* lp_w   = (const float*)d_in[5];
    const float* lp_b   = (const float*)d_in[6];
    const float* bln_w  = (const float*)d_in[7];
    const float* bln_b  = (const float*)d_in[8];
    const float* in_w   = (const float*)d_in[9];
    const float* conv_w = (const float*)d_in[10];
    const float* conv_b = (const float*)d_in[11];
    const float* xp_w   = (const float*)d_in[12];
    const float* dt_w   = (const float*)d_in[13];
    const float* dt_b   = (const float*)d_in[14];
    const float* A_log  = (const float*)d_in[15];
    const float* Ds     = (const float*)d_in[16];
    const float* on_w   = (const float*)d_in[17];
    const float* on_b   = (const float*)d_in[18];
    const float* out_w  = (const float*)d_in[19];
    float* out = (float*)d_out;

    float *xT, *pe, *cat, *xh, *hbuf, *xz, *xc, *xdbl, *dts, *ys, *ybuf;
    int* rowmap;
    cudaGetSymbolAddress((void**)&xT,   g_xT);
    cudaGetSymbolAddress((void**)&pe,   g_pe);
    cudaGetSymbolAddress((void**)&cat,  g_cat);
    cudaGetSymbolAddress((void**)&xh,   g_xh);
    cudaGetSymbolAddress((void**)&hbuf, g_h);
    cudaGetSymbolAddress((void**)&xz,   g_xz);
    cudaGetSymbolAddress((void**)&xc,   g_xc);
    cudaGetSymbolAddress((void**)&xdbl, g_xdbl);
    cudaGetSymbolAddress((void**)&dts,  g_dts);
    cudaGetSymbolAddress((void**)&ys,   g_ys);
    cudaGetSymbolAddress((void**)&ybuf, g_y);
    cudaGetSymbolAddress((void**)&rowmap, g_rowmap);

    // x (B,768,16,16) -> xT (B,256,768)
    transpose_kernel<<<dim3(256 / 32, 768 / 32, 2), dim3(32, 8)>>>(x, xT, 768, 256);
    rowmap_init<<<8, 1024>>>();

    // patch-expand GEMM: (512 x 1536 x 768)
    gemm_tn<<<dim3(12, 4, 1), 256>>>(xT, pe_w, nullptr, pe, 512, 1536, 768,
                                     768, 768, 1536, 0, 0, 1, 0, 0, nullptr, 0, 0);
    // expand-reshape + LN + concat skip -> cat (2048 x 768)
    pe_cat_kernel<<<2048, 128>>>(pe, skip, pe_nw, pe_nb, cat);
    // linear proj: (2048 x 384 x 768) + bias -> xh
    gemm_tn<<<dim3(3, 16, 1), 256>>>(cat, lp_w, lp_b, xh, 2048, 384, 768,
                                     768, 768, 384, 0, 0, 1, 0, 0, nullptr, 0, 1);

    for (int layer = 0; layer < 2; layer++) {
        ln384_kernel<<<2048, 128>>>(xh, hbuf, bln_w + layer * 384, bln_b + layer * 384);
        // in_proj: (2048 x 1536 x 384)
        gemm_tn<<<dim3(12, 16, 1), 256>>>(hbuf, in_w + (long)layer * 1536 * 384, nullptr, xz,
                                          2048, 1536, 384, 384, 384, 1536,
                                          0, 0, 1, 0, 0, nullptr, 0, 0);
        // depthwise conv + silu -> xc (NHWC)
        conv_kernel<<<2048, 256>>>(xz, conv_w + (long)layer * 768 * 9,
                                   conv_b + layer * 768, xc);
        // x_proj: 8 x (1024 x 80 x 768) with direction row-permutation
        gemm_tn<<<dim3(1, 8, 8), 256>>>(xc, xp_w + (long)layer * 4 * 80 * 768, nullptr, xdbl,
                                        1024, 80, 768, 768, 768, 80,
                                        0, (long)80 * 768, 4, 0, (long)1024 * 80,
                                        rowmap, 1024, 0);
        // dt_proj: 8 x (1024 x 768 x 48) + bias + softplus
        gemm_tn<<<dim3(6, 8, 8), 256>>>(xdbl, dt_w + (long)layer * 4 * 768 * 48,
                                        dt_b + (long)layer * 4 * 768, dts,
                                        1024, 768, 48, 80, 48, 768,
                                        (long)1024 * 80, (long)768 * 48, 4, 768,
                                        (long)1024 * 768, nullptr, 0, 1 | 2);
        // selective scan (one thread per (g,d,n))
        scan_kernel<<<dim3(8, 96), 128>>>(dts, xc, xdbl,
                                          A_log + (long)layer * 4 * 768 * 16,
                                          Ds + (long)layer * 4 * 768, ys);
        // merge directions + out-LN + silu(z) gate
        combine_kernel<<<2048, 256>>>(ys, xz, on_w + layer * 768, on_b + layer * 768, ybuf);
        // out_proj + residual: (2048 x 384 x 768), accumulate into xh
        gemm_tn<<<dim3(3, 16, 1), 256>>>(ybuf, out_w + (long)layer * 384 * 768, nullptr, xh,
                                         2048, 384, 768, 768, 768, 384,
                                         0, 0, 1, 0, 0, nullptr, 0, 4);
    }

    // xh (B,1024,384) -> out (B,384,32,32)
    transpose_kernel<<<dim3(384 / 32, 1024 / 32, 2), dim3(32, 8)>>>(xh, out, 1024, 384);
}

// round 5
// speedup vs baseline: 2.0151x; 1.1220x over previous
#include <cuda_runtime.h>
#include <cuda_bf16.h>
#include <math.h>
#include <stdint.h>

// ---------------------------------------------------------------------------
// Problem constants
//   B=2, in spatial 16x16 -> expanded 32x32 (L=1024, S=B*L=2048)
//   out_dim=384, Di=768, N=16, R=48, K=4 directions, G=8 groups, depth=2
// ---------------------------------------------------------------------------

#define S_TOT 2048          // B * 32 * 32
#define L_LEN 1024
#define DI    768
#define DOUT  384
#define NST   16
#define CT    80            // R + 2N
#define RLOW  48

// ------------------------- scratch (static device mem) ---------------------
__device__ float g_xT  [2 * 256 * 768];
__device__ float g_pe  [512 * 1536];
__device__ float g_cat [S_TOT * 768];
__device__ float g_xh  [S_TOT * DOUT];
__device__ float g_h   [S_TOT * DOUT];
__device__ float g_xz  [S_TOT * 1536];
__device__ float g_xc  [S_TOT * DI];
__device__ float g_xdbl[8 * L_LEN * CT];
__device__ float g_dts [8 * L_LEN * DI];
__device__ float g_ys  [8 * L_LEN * DI];
__device__ float g_y   [S_TOT * DI];
__device__ int   g_rowmap[8 * L_LEN];

// ------------------------- helpers ------------------------------------------
__device__ __forceinline__ float block_reduce_sum(float v, float* red) {
#pragma unroll
    for (int o = 16; o > 0; o >>= 1) v += __shfl_xor_sync(0xffffffffu, v, o);
    int warp = threadIdx.x >> 5;
    if ((threadIdx.x & 31) == 0) red[warp] = v;
    __syncthreads();
    int nw = blockDim.x >> 5;
    float s = 0.f;
    for (int i = 0; i < nw; i++) s += red[i];
    __syncthreads();
    return s;
}

__device__ __forceinline__ int swap_l(int l) { return ((l & 31) << 5) | (l >> 5); }

__device__ __forceinline__ float silu_f(float v) { return v / (1.f + __expf(-v)); }

__device__ __forceinline__ void cpa16(unsigned int smem, const void* g, int srcBytes) {
    asm volatile("cp.async.cg.shared.global [%0], [%1], 16, %2;\n"
                 :: "r"(smem), "l"(g), "r"(srcBytes));
}
__device__ __forceinline__ void cpa_commit() {
    asm volatile("cp.async.commit_group;\n");
}
template <int N>
__device__ __forceinline__ void cpa_wait() {
    asm volatile("cp.async.wait_group %0;\n" :: "n"(N));
}

// ------------------------- 64x64x16 cp.async double-buffered SGEMM ----------
// C = A * W^T.  A: (M x Kdim) rows (optional rowmap), W: (Ncols x Kdim).
// flags: 1 = add bias[col], 2 = softplus, 4 = accumulate into C.
// Requirements: M % 64 == 0, Kdim % 16 == 0, Ncols % 4 == 0, lda/ldw % 4 == 0.
#define BM 64
#define BN 64
#define BKG 16
#define SROW 20   // smem row stride in floats (16 + 4 pad, keeps 16B alignment)

__global__ void gemm64(const float* __restrict__ A, const float* __restrict__ W,
                       const float* __restrict__ bias, float* __restrict__ C,
                       int M, int Ncols, int Kdim, int lda, int ldw, int ldc,
                       long aBatch, long wBatch, int wMod, long biasBatch, long cBatch,
                       const int* __restrict__ rowmap, int rmBatch, int flags)
{
    __shared__ float As[2][BM][SROW];
    __shared__ float Ws[2][BN][SROW];

    const int z = blockIdx.z;
    const int wz = (wMod > 1) ? (z % wMod) : 0;
    const float* Ab = A + (long)z * aBatch;
    const float* Wb = W + (long)wz * wBatch;
    const float* biasb = bias ? (bias + (long)wz * biasBatch) : (const float*)0;
    float* Cb = C + (long)z * cBatch;
    const int* rm = rowmap ? (rowmap + (long)z * rmBatch) : (const int*)0;

    const int m0 = blockIdx.y * BM, n0 = blockIdx.x * BN;
    const int tid = threadIdx.x;
    const int ty = tid >> 4, tx = tid & 15;

    // ------- per-thread copy assignment: 2 float4 chunks of A and of W ------
    // chunk c in {0,1}: idx = tid*2 + c; m = idx/4 (0..63), k4 = idx%4
    int cm[2], ck[2];
    const float* agp[2];
    const float* wgp[2];
    int wbytes[2];
#pragma unroll
    for (int c = 0; c < 2; c++) {
        int idx = tid * 2 + c;
        cm[c] = idx >> 2;
        ck[c] = (idx & 3) * 4;
        int arow = m0 + cm[c];
        if (rm) arow = rm[arow];
        agp[c] = Ab + (long)arow * lda + ck[c];
        int wrow = n0 + cm[c];
        bool wok = wrow < Ncols;
        wgp[c] = wok ? (Wb + (long)wrow * ldw + ck[c]) : Wb;
        wbytes[c] = wok ? 16 : 0;
    }
    unsigned int smA_base = (unsigned int)__cvta_generic_to_shared(&As[0][0][0]);
    unsigned int smW_base = (unsigned int)__cvta_generic_to_shared(&Ws[0][0][0]);

    float acc[8][4];
#pragma unroll
    for (int i = 0; i < 8; i++)
#pragma unroll
        for (int j = 0; j < 4; j++) acc[i][j] = 0.f;

    const int T = Kdim / BKG;

    // prefetch tile 0 into stage 0
#pragma unroll
    for (int c = 0; c < 2; c++) {
        unsigned int addrA = smA_base + (unsigned int)(((0 * BM + cm[c]) * SROW + ck[c]) * 4);
        cpa16(addrA, agp[c], 16);
        unsigned int addrW = smW_base + (unsigned int)(((0 * BN + cm[c]) * SROW + ck[c]) * 4);
        cpa16(addrW, wgp[c], wbytes[c]);
    }
    cpa_commit();

    for (int t = 0; t < T; t++) {
        int s = t & 1;
        if (t + 1 < T) {
            int s2 = (t + 1) & 1;
            int koff = (t + 1) * BKG;
#pragma unroll
            for (int c = 0; c < 2; c++) {
                unsigned int addrA = smA_base + (unsigned int)(((s2 * BM + cm[c]) * SROW + ck[c]) * 4);
                cpa16(addrA, agp[c] + koff, 16);
                unsigned int addrW = smW_base + (unsigned int)(((s2 * BN + cm[c]) * SROW + ck[c]) * 4);
                cpa16(addrW, wgp[c] + koff, wbytes[c]);
            }
            cpa_commit();
            cpa_wait<1>();
        } else {
            cpa_wait<0>();
        }
        __syncthreads();

#pragma unroll
        for (int kk4 = 0; kk4 < 4; kk4++) {
            float4 av[8], wv[4];
#pragma unroll
            for (int i = 0; i < 8; i++)
                av[i] = *(const float4*)&As[s][ty * 8 + i][kk4 * 4];
#pragma unroll
            for (int j = 0; j < 4; j++)
                wv[j] = *(const float4*)&Ws[s][tx * 4 + j][kk4 * 4];
#pragma unroll
            for (int i = 0; i < 8; i++) {
#pragma unroll
                for (int j = 0; j < 4; j++) {
                    acc[i][j] = fmaf(av[i].x, wv[j].x, acc[i][j]);
                    acc[i][j] = fmaf(av[i].y, wv[j].y, acc[i][j]);
                    acc[i][j] = fmaf(av[i].z, wv[j].z, acc[i][j]);
                    acc[i][j] = fmaf(av[i].w, wv[j].w, acc[i][j]);
                }
            }
        }
        __syncthreads();
    }

    // ------------------------------ epilogue --------------------------------
    int ncol = n0 + tx * 4;
    if (ncol < Ncols) {
        float4 bv = make_float4(0.f, 0.f, 0.f, 0.f);
        if (flags & 1) bv = *(const float4*)&biasb[ncol];
#pragma unroll
        for (int i = 0; i < 8; i++) {
            int row = m0 + ty * 8 + i;
            float v[4];
#pragma unroll
            for (int j = 0; j < 4; j++) v[j] = acc[i][j];
            if (flags & 1) { v[0] += bv.x; v[1] += bv.y; v[2] += bv.z; v[3] += bv.w; }
            if (flags & 2) {
#pragma unroll
                for (int j = 0; j < 4; j++)
                    v[j] = (v[j] > 20.f) ? v[j] : log1pf(__expf(v[j]));
            }
            float4* cp = (float4*)&Cb[(long)row * ldc + ncol];
            if (flags & 4) {
                float4 old = *cp;
                v[0] += old.x; v[1] += old.y; v[2] += old.z; v[3] += old.w;
            }
            *cp = make_float4(v[0], v[1], v[2], v[3]);
        }
    }
}

// ------------------------- transpose (per-batch rows x cols -> cols x rows) -
__global__ void transpose_kernel(const float* __restrict__ src, float* __restrict__ dst,
                                 int rows, int cols)
{
    __shared__ float tile[32][33];
    int c0 = blockIdx.x * 32, r0 = blockIdx.y * 32, bz = blockIdx.z;
    const float* s = src + (long)bz * rows * cols;
    float* d = dst + (long)bz * rows * cols;
    for (int i = threadIdx.y; i < 32; i += 8)
        tile[i][threadIdx.x] = s[(long)(r0 + i) * cols + c0 + threadIdx.x];
    __syncthreads();
    for (int i = threadIdx.y; i < 32; i += 8)
        d[(long)(c0 + i) * rows + r0 + threadIdx.x] = tile[threadIdx.x][i];
}

// ------------------------- rowmap init --------------------------------------
__global__ void rowmap_init()
{
    int g = blockIdx.x, l = threadIdx.x;
    int k = g & 3, b = g >> 2;
    int s;
    if (k == 0) s = l;
    else if (k == 1) s = swap_l(l);
    else if (k == 2) s = 1023 - l;
    else { int m = 1023 - l; s = swap_l(m); }
    g_rowmap[g * L_LEN + l] = b * L_LEN + s;
}

// ------------------------- patch-expand LN + concat skip --------------------
__global__ void pe_cat_kernel(const float* __restrict__ pe, const float* __restrict__ skip,
                              const float* __restrict__ nw, const float* __restrict__ nb,
                              float* __restrict__ cat)
{
    int pix = blockIdx.x;                    // b*1024 + Y*32 + X
    int b = pix >> 10, Y = (pix >> 5) & 31, X = pix & 31;
    int h = Y >> 1, p = Y & 1, w = X >> 1, q = X & 1;
    const float* src = pe + (long)(b * 256 + h * 16 + w) * 1536 + (p * 2 + q) * 384;

    __shared__ float red[32];
    float v[3]; float ssum = 0.f;
#pragma unroll
    for (int j = 0; j < 3; j++) { v[j] = src[threadIdx.x + j * 128]; ssum += v[j]; }
    float mean = block_reduce_sum(ssum, red) * (1.f / 384.f);
    float vs = 0.f;
#pragma unroll
    for (int j = 0; j < 3; j++) { float d = v[j] - mean; vs += d * d; }
    float var = block_reduce_sum(vs, red) * (1.f / 384.f);
    float rstd = rsqrtf(var + 1e-5f);

    float* dst = cat + (long)pix * 768;
#pragma unroll
    for (int j = 0; j < 3; j++) {
        int c = threadIdx.x + j * 128;
        dst[c] = (v[j] - mean) * rstd * nw[c] + nb[c];
    }
    const float* sp = skip + (long)b * 384 * 1024 + (Y * 32 + X);
#pragma unroll
    for (int j = 0; j < 3; j++) {
        int c = threadIdx.x + j * 128;
        dst[384 + c] = sp[(long)c * 1024];
    }
}

// ------------------------- LN over 384 ---------------------------------------
__global__ void ln384_kernel(const float* __restrict__ in, float* __restrict__ out,
                             const float* __restrict__ w, const float* __restrict__ b)
{
    int row = blockIdx.x;
    const float* src = in + (long)row * 384;
    __shared__ float red[32];
    float v[3]; float ssum = 0.f;
#pragma unroll
    for (int j = 0; j < 3; j++) { v[j] = src[threadIdx.x + j * 128]; ssum += v[j]; }
    float mean = block_reduce_sum(ssum, red) * (1.f / 384.f);
    float vs = 0.f;
#pragma unroll
    for (int j = 0; j < 3; j++) { float d = v[j] - mean; vs += d * d; }
    float var = block_reduce_sum(vs, red) * (1.f / 384.f);
    float rstd = rsqrtf(var + 1e-5f);
    float* dst = out + (long)row * 384;
#pragma unroll
    for (int j = 0; j < 3; j++) {
        int c = threadIdx.x + j * 128;
        dst[c] = (v[j] - mean) * rstd * w[c] + b[c];
    }
}

// ------------------------- depthwise 3x3 conv + bias + silu ------------------
__global__ void conv_kernel(const float* __restrict__ xz, const float* __restrict__ cw,
                            const float* __restrict__ cb, float* __restrict__ xc)
{
    int pix = blockIdx.x;
    int b = pix >> 10, Y = (pix >> 5) & 31, X = pix & 31;
    int t = threadIdx.x;
    float acc[3] = {0.f, 0.f, 0.f};
    for (int dy = -1; dy <= 1; dy++) {
        int yy = Y + dy; if ((unsigned)yy >= 32u) continue;
        for (int dx = -1; dx <= 1; dx++) {
            int xx = X + dx; if ((unsigned)xx >= 32u) continue;
            const float* row = xz + (long)(b * 1024 + yy * 32 + xx) * 1536;
            int widx = (dy + 1) * 3 + (dx + 1);
#pragma unroll
            for (int j = 0; j < 3; j++) {
                int c = t + j * 256;
                acc[j] = fmaf(row[c], cw[c * 9 + widx], acc[j]);
            }
        }
    }
    float* dst = xc + (long)pix * 768;
#pragma unroll
    for (int j = 0; j < 3; j++) {
        int c = t + j * 256;
        float v = acc[j] + cb[c];
        dst[c] = silu_f(v);
    }
}

// ------------------------- selective scan -----------------------------------
// one thread per (g, d, n): 16 threads cooperate on one (g,d) lane, each
// owning a single state n. y is reduced across the 16-lane group via shfl.
__global__ void scan_kernel(const float* __restrict__ dts, const float* __restrict__ xc,
                            const float* __restrict__ xdbl, const float* __restrict__ A_log,
                            const float* __restrict__ Ds, float* __restrict__ ys)
{
    int g = blockIdx.x;
    int k = g & 3, b = g >> 2;
    int tid = threadIdx.x;
    int n = tid & 15;
    int d = blockIdx.y * 8 + (tid >> 4);

    float A = -__expf(A_log[((long)(k * DI + d)) * NST + n]);
    float h = 0.f;
    float Dv = Ds[k * DI + d];

    const float* dtp = dts + (long)g * L_LEN * DI + d;
    const float* xdp = xdbl + (long)g * L_LEN * CT;
    const float* xcb = xc + (long)b * L_LEN * DI + d;
    float* yp = ys + (long)g * L_LEN * DI + d;

    for (int l = 0; l < L_LEN; l++) {
        int s;
        if (k == 0) s = l;
        else if (k == 1) s = swap_l(l);
        else if (k == 2) s = 1023 - l;
        else { int m = 1023 - l; s = swap_l(m); }

        float dt = dtp[(long)l * DI];          // broadcast within 16-lane group
        float u  = xcb[(long)s * DI];
        const float* bc = xdp + l * CT;
        float Bn = bc[RLOW + n];
        float Cn = bc[RLOW + NST + n];

        float e = __expf(dt * A);
        h = fmaf(e, h, dt * u * Bn);
        float t = h * Cn;
        t += __shfl_xor_sync(0xffffffffu, t, 1);
        t += __shfl_xor_sync(0xffffffffu, t, 2);
        t += __shfl_xor_sync(0xffffffffu, t, 4);
        t += __shfl_xor_sync(0xffffffffu, t, 8);
        if (n == 0) yp[(long)l * DI] = fmaf(Dv, u, t);
    }
}

// ------------------------- combine 4 dirs + out-LN + silu(z) gate ------------
__global__ void combine_kernel(const float* __restrict__ ys, const float* __restrict__ xz,
                               const float* __restrict__ onw, const float* __restrict__ onb,
                               float* __restrict__ yout)
{
    int bs = blockIdx.x;                 // b*1024 + s
    int b = bs >> 10, s = bs & 1023;
    int sw = swap_l(s);
    long base0 = ((long)(b * 4 + 0) * L_LEN + s)          * DI;
    long base1 = ((long)(b * 4 + 1) * L_LEN + sw)         * DI;
    long base2 = ((long)(b * 4 + 2) * L_LEN + (1023 - s)) * DI;
    long base3 = ((long)(b * 4 + 3) * L_LEN + (1023 - sw))* DI;

    __shared__ float red[32];
    float v[3]; float ssum = 0.f;
#pragma unroll
    for (int j = 0; j < 3; j++) {
        int c = threadIdx.x + j * 256;
        v[j] = ys[base0 + c] + ys[base1 + c] + ys[base2 + c] + ys[base3 + c];
        ssum += v[j];
    }
    float mean = block_reduce_sum(ssum, red) * (1.f / 768.f);
    float vs = 0.f;
#pragma unroll
    for (int j = 0; j < 3; j++) { float d = v[j] - mean; vs += d * d; }
    float var = block_reduce_sum(vs, red) * (1.f / 768.f);
    float rstd = rsqrtf(var + 1e-5f);

#pragma unroll
    for (int j = 0; j < 3; j++) {
        int c = threadIdx.x + j * 256;
        float zz = xz[(long)bs * 1536 + 768 + c];
        yout[(long)bs * DI + c] = ((v[j] - mean) * rstd * onw[c] + onb[c]) * silu_f(zz);
    }
}

// ---------------------------------------------------------------------------
extern "C" void kernel_launch(void* const* d_in, const int* in_sizes, int n_in,
                              void* d_out, int out_size)
{
    const float* x      = (const float*)d_in[0];
    const float* skip   = (const float*)d_in[1];
    const float* pe_w   = (const float*)d_in[2];
    const float* pe_nw  = (const float*)d_in[3];
    const float* pe_nb  = (const float*)d_in[4];
    const float* lp_w   = (const float*)d_in[5];
    const float* lp_b   = (const float*)d_in[6];
    const float* bln_w  = (const float*)d_in[7];
    const float* bln_b  = (const float*)d_in[8];
    const float* in_w   = (const float*)d_in[9];
    const float* conv_w = (const float*)d_in[10];
    const float* conv_b = (const float*)d_in[11];
    const float* xp_w   = (const float*)d_in[12];
    const float* dt_w   = (const float*)d_in[13];
    const float* dt_b   = (const float*)d_in[14];
    const float* A_log  = (const float*)d_in[15];
    const float* Ds     = (const float*)d_in[16];
    const float* on_w   = (const float*)d_in[17];
    const float* on_b   = (const float*)d_in[18];
    const float* out_w  = (const float*)d_in[19];
    float* out = (float*)d_out;

    float *xT, *pe, *cat, *xh, *hbuf, *xz, *xc, *xdbl, *dts, *ys, *ybuf;
    int* rowmap;
    cudaGetSymbolAddress((void**)&xT,   g_xT);
    cudaGetSymbolAddress((void**)&pe,   g_pe);
    cudaGetSymbolAddress((void**)&cat,  g_cat);
    cudaGetSymbolAddress((void**)&xh,   g_xh);
    cudaGetSymbolAddress((void**)&hbuf, g_h);
    cudaGetSymbolAddress((void**)&xz,   g_xz);
    cudaGetSymbolAddress((void**)&xc,   g_xc);
    cudaGetSymbolAddress((void**)&xdbl, g_xdbl);
    cudaGetSymbolAddress((void**)&dts,  g_dts);
    cudaGetSymbolAddress((void**)&ys,   g_ys);
    cudaGetSymbolAddress((void**)&ybuf, g_y);
    cudaGetSymbolAddress((void**)&rowmap, g_rowmap);

    // x (B,768,16,16) -> xT (B,256,768)
    transpose_kernel<<<dim3(256 / 32, 768 / 32, 2), dim3(32, 8)>>>(x, xT, 768, 256);
    rowmap_init<<<8, 1024>>>();

    // patch-expand GEMM: (512 x 1536 x 768)  grid 24x8 = 192 blocks
    gemm64<<<dim3(24, 8, 1), 128>>>(xT, pe_w, nullptr, pe, 512, 1536, 768,
                                    768, 768, 1536, 0, 0, 1, 0, 0, nullptr, 0, 0);
    // expand-reshape + LN + concat skip -> cat (2048 x 768)
    pe_cat_kernel<<<2048, 128>>>(pe, skip, pe_nw, pe_nb, cat);
    // linear proj: (2048 x 384 x 768) + bias -> xh   grid 6x32 = 192
    gemm64<<<dim3(6, 32, 1), 128>>>(cat, lp_w, lp_b, xh, 2048, 384, 768,
                                    768, 768, 384, 0, 0, 1, 0, 0, nullptr, 0, 1);

    for (int layer = 0; layer < 2; layer++) {
        ln384_kernel<<<2048, 128>>>(xh, hbuf, bln_w + layer * 384, bln_b + layer * 384);
        // in_proj: (2048 x 1536 x 384)  grid 24x32 = 768
        gemm64<<<dim3(24, 32, 1), 128>>>(hbuf, in_w + (long)layer * 1536 * 384, nullptr, xz,
                                         2048, 1536, 384, 384, 384, 1536,
                                         0, 0, 1, 0, 0, nullptr, 0, 0);
        // depthwise conv + silu -> xc (NHWC)
        conv_kernel<<<2048, 256>>>(xz, conv_w + (long)layer * 768 * 9,
                                   conv_b + layer * 768, xc);
        // x_proj: 8 x (1024 x 80 x 768) with direction row-permutation  grid 2x16x8 = 256
        gemm64<<<dim3(2, 16, 8), 128>>>(xc, xp_w + (long)layer * 4 * 80 * 768, nullptr, xdbl,
                                        1024, 80, 768, 768, 768, 80,
                                        0, (long)80 * 768, 4, 0, (long)1024 * 80,
                                        rowmap, 1024, 0);
        // dt_proj: 8 x (1024 x 768 x 48) + bias + softplus  grid 12x16x8 = 1536
        gemm64<<<dim3(12, 16, 8), 128>>>(xdbl, dt_w + (long)layer * 4 * 768 * 48,
                                         dt_b + (long)layer * 4 * 768, dts,
                                         1024, 768, 48, 80, 48, 768,
                                         (long)1024 * 80, (long)768 * 48, 4, 768,
                                         (long)1024 * 768, nullptr, 0, 1 | 2);
        // selective scan (one thread per (g,d,n))
        scan_kernel<<<dim3(8, 96), 128>>>(dts, xc, xdbl,
                                          A_log + (long)layer * 4 * 768 * 16,
                                          Ds + (long)layer * 4 * 768, ys);
        // merge directions + out-LN + silu(z) gate
        combine_kernel<<<2048, 256>>>(ys, xz, on_w + layer * 768, on_b + layer * 768, ybuf);
        // out_proj + residual: (2048 x 384 x 768), accumulate into xh  grid 6x32 = 192
        gemm64<<<dim3(6, 32, 1), 128>>>(ybuf, out_w + (long)layer * 384 * 768, nullptr, xh,
                                        2048, 384, 768, 768, 768, 384,
                                        0, 0, 1, 0, 0, nullptr, 0, 4);
    }

    // xh (B,1024,384) -> out (B,384,32,32)
    transpose_kernel<<<dim3(384 / 32, 1024 / 32, 2), dim3(32, 8)>>>(xh, out, 1024, 384);
}

// round 6
// speedup vs baseline: 3.0473x; 1.5122x over previous
#include <cuda_runtime.h>
#include <cuda_bf16.h>
#include <math.h>
#include <stdint.h>

// ---------------------------------------------------------------------------
// B=2, 32x32 spatial (L=1024, S=2048), out_dim=384, Di=768, N=16, R=48, K=4
// ---------------------------------------------------------------------------

#define S_TOT 2048
#define L_LEN 1024
#define DI    768
#define DOUT  384
#define NST   16
#define CT    80
#define RLOW  48

__device__ float g_xT  [2 * 256 * 768];
__device__ float g_pe  [512 * 1536];
__device__ float g_cat [S_TOT * 768];
__device__ float g_xh  [S_TOT * DOUT];
__device__ float g_h   [S_TOT * DOUT];
__device__ float g_xz  [S_TOT * 1536];
__device__ float g_xc  [S_TOT * DI];
__device__ float g_xdbl[8 * L_LEN * CT];
__device__ float g_dts [8 * L_LEN * DI];
__device__ float g_ys  [8 * L_LEN * DI];
__device__ float g_y   [S_TOT * DI];
__device__ int   g_rowmap[8 * L_LEN];

// ------------------------- helpers ------------------------------------------
__device__ __forceinline__ float block_reduce_sum(float v, float* red) {
#pragma unroll
    for (int o = 16; o > 0; o >>= 1) v += __shfl_xor_sync(0xffffffffu, v, o);
    int warp = threadIdx.x >> 5;
    if ((threadIdx.x & 31) == 0) red[warp] = v;
    __syncthreads();
    int nw = blockDim.x >> 5;
    float s = 0.f;
    for (int i = 0; i < nw; i++) s += red[i];
    __syncthreads();
    return s;
}

__device__ __forceinline__ int swap_l(int l) { return ((l & 31) << 5) | (l >> 5); }
__device__ __forceinline__ float silu_f(float v) { return v / (1.f + __expf(-v)); }

__device__ __forceinline__ void mma16816(float* d, const unsigned* a, const unsigned* b) {
    asm volatile(
        "mma.sync.aligned.m16n8k16.row.col.f32.bf16.bf16.f32 "
        "{%0,%1,%2,%3}, {%4,%5,%6,%7}, {%8,%9}, {%0,%1,%2,%3};"
        : "+f"(d[0]), "+f"(d[1]), "+f"(d[2]), "+f"(d[3])
        : "r"(a[0]), "r"(a[1]), "r"(a[2]), "r"(a[3]), "r"(b[0]), "r"(b[1]));
}

// convert 2 floats -> (hi bf16x2, lo bf16x2)
__device__ __forceinline__ void split2(float f0, float f1, unsigned& hi, unsigned& lo) {
    __nv_bfloat162 h = __floats2bfloat162_rn(f0, f1);
    float h0 = __low2float(h), h1 = __high2float(h);
    __nv_bfloat162 l = __floats2bfloat162_rn(f0 - h0, f1 - h1);
    hi = *(unsigned*)&h;
    lo = *(unsigned*)&l;
}

// ---------------- split-bf16 tensor-core GEMM: C = A * W^T ------------------
// Tile 64x64x32, 128 threads, warp grid 2x2 (warp tile 32x32).
// flags: 1 = +bias[col], 2 = softplus, 4 = accumulate into C.
// M%64==0, Kdim%16==0, Ncols%2==0, lda/ldw 4-float aligned.
#define GBM 64
#define GBN 64
#define GBK 32
#define GSR 20   // smem row stride in uint32 (16 pairs + 4 pad)

__global__ void gemm_tc(const float* __restrict__ A, const float* __restrict__ W,
                        const float* __restrict__ bias, float* __restrict__ C,
                        int M, int Ncols, int Kdim, int lda, int ldw, int ldc,
                        long aBatch, long wBatch, int wMod, long biasBatch, long cBatch,
                        const int* __restrict__ rowmap, int rmBatch, int flags)
{
    __shared__ unsigned As_hi[GBM][GSR], As_lo[GBM][GSR];
    __shared__ unsigned Ws_hi[GBN][GSR], Ws_lo[GBN][GSR];

    const int z = blockIdx.z;
    const int wz = (wMod > 1) ? (z % wMod) : 0;
    const float* Ab = A + (long)z * aBatch;
    const float* Wb = W + (long)wz * wBatch;
    const float* biasb = bias ? (bias + (long)wz * biasBatch) : (const float*)0;
    float* Cb = C + (long)z * cBatch;
    const int* rm = rowmap ? (rowmap + (long)z * rmBatch) : (const int*)0;

    const int m0 = blockIdx.y * GBM, n0 = blockIdx.x * GBN;
    const int tid = threadIdx.x;
    const int wid = tid >> 5, lane = tid & 31;
    const int wm = (wid >> 1) * 32, wn = (wid & 1) * 32;
    const int gq = lane >> 2, qq = lane & 3;

    // loader assignment: thread -> (row, half); half covers 16 k-floats
    const int lrow = tid >> 1, lhalf = tid & 1;
    int arow = m0 + lrow;
    if (rm) arow = rm[arow];
    const float* aRow = Ab + (long)arow * lda + lhalf * 16;
    const int wrow = n0 + lrow;
    const bool wok = wrow < Ncols;
    const float* wRow = wok ? (Wb + (long)wrow * ldw + lhalf * 16) : Wb;

    float acc[2][4][4];
#pragma unroll
    for (int i = 0; i < 2; i++)
#pragma unroll
        for (int j = 0; j < 4; j++)
#pragma unroll
            for (int f = 0; f < 4; f++) acc[i][j][f] = 0.f;

    const int T = (Kdim + GBK - 1) / GBK;

    float4 pfA[4], pfW[4];
    const float4 z4 = make_float4(0.f, 0.f, 0.f, 0.f);

    // ---- prefetch tile 0 ----
    {
        bool kv = (0 + lhalf * 16) < Kdim;
#pragma unroll
        for (int q = 0; q < 4; q++) {
            pfA[q] = kv ? *(const float4*)(aRow + q * 4) : z4;
            pfW[q] = (kv && wok) ? *(const float4*)(wRow + q * 4) : z4;
        }
    }

    for (int t = 0; t < T; t++) {
        // store prefetched tile t into smem (with split-bf16 conversion)
        {
            unsigned ah[8], al[8], wh[8], wl[8];
            const float* fa = (const float*)pfA;
            const float* fw = (const float*)pfW;
#pragma unroll
            for (int p = 0; p < 8; p++) {
                split2(fa[2 * p], fa[2 * p + 1], ah[p], al[p]);
                split2(fw[2 * p], fw[2 * p + 1], wh[p], wl[p]);
            }
            *(uint4*)&As_hi[lrow][lhalf * 8]     = make_uint4(ah[0], ah[1], ah[2], ah[3]);
            *(uint4*)&As_hi[lrow][lhalf * 8 + 4] = make_uint4(ah[4], ah[5], ah[6], ah[7]);
            *(uint4*)&As_lo[lrow][lhalf * 8]     = make_uint4(al[0], al[1], al[2], al[3]);
            *(uint4*)&As_lo[lrow][lhalf * 8 + 4] = make_uint4(al[4], al[5], al[6], al[7]);
            *(uint4*)&Ws_hi[lrow][lhalf * 8]     = make_uint4(wh[0], wh[1], wh[2], wh[3]);
            *(uint4*)&Ws_hi[lrow][lhalf * 8 + 4] = make_uint4(wh[4], wh[5], wh[6], wh[7]);
            *(uint4*)&Ws_lo[lrow][lhalf * 8]     = make_uint4(wl[0], wl[1], wl[2], wl[3]);
            *(uint4*)&Ws_lo[lrow][lhalf * 8 + 4] = make_uint4(wl[4], wl[5], wl[6], wl[7]);
        }
        __syncthreads();

        // issue global loads for tile t+1
        if (t + 1 < T) {
            int k0 = (t + 1) * GBK;
            bool kv = (k0 + lhalf * 16) < Kdim;
#pragma unroll
            for (int q = 0; q < 4; q++) {
                pfA[q] = kv ? *(const float4*)(aRow + k0 + q * 4) : z4;
                pfW[q] = (kv && wok) ? *(const float4*)(wRow + k0 + q * 4) : z4;
            }
        }

        // compute tile t
#pragma unroll
        for (int kk = 0; kk < 2; kk++) {
            const int kb = kk * 8;
            unsigned ahi[2][4], alo[2][4], bhi[4][2], blo[4][2];
#pragma unroll
            for (int i = 0; i < 2; i++) {
                int r = wm + i * 16 + gq;
                ahi[i][0] = As_hi[r][kb + qq];
                ahi[i][1] = As_hi[r + 8][kb + qq];
                ahi[i][2] = As_hi[r][kb + 4 + qq];
                ahi[i][3] = As_hi[r + 8][kb + 4 + qq];
                alo[i][0] = As_lo[r][kb + qq];
                alo[i][1] = As_lo[r + 8][kb + qq];
                alo[i][2] = As_lo[r][kb + 4 + qq];
                alo[i][3] = As_lo[r + 8][kb + 4 + qq];
            }
#pragma unroll
            for (int j = 0; j < 4; j++) {
                int r = wn + j * 8 + gq;
                bhi[j][0] = Ws_hi[r][kb + qq];
                bhi[j][1] = Ws_hi[r][kb + 4 + qq];
                blo[j][0] = Ws_lo[r][kb + qq];
                blo[j][1] = Ws_lo[r][kb + 4 + qq];
            }
#pragma unroll
            for (int i = 0; i < 2; i++)
#pragma unroll
                for (int j = 0; j < 4; j++) {
                    mma16816(acc[i][j], ahi[i], bhi[j]);
                    mma16816(acc[i][j], ahi[i], blo[j]);
                    mma16816(acc[i][j], alo[i], bhi[j]);
                }
        }
        __syncthreads();
    }

    // ------------------------------ epilogue --------------------------------
#pragma unroll
    for (int i = 0; i < 2; i++) {
        int r0 = m0 + wm + i * 16 + gq;
        int r1 = r0 + 8;
#pragma unroll
        for (int j = 0; j < 4; j++) {
            int col = n0 + wn + j * 8 + qq * 2;
            if (col >= Ncols) continue;
            float v0 = acc[i][j][0], v1 = acc[i][j][1];
            float v2 = acc[i][j][2], v3 = acc[i][j][3];
            if (flags & 1) {
                float b0 = biasb[col], b1 = biasb[col + 1];
                v0 += b0; v1 += b1; v2 += b0; v3 += b1;
            }
            if (flags & 2) {
                v0 = (v0 > 20.f) ? v0 : log1pf(__expf(v0));
                v1 = (v1 > 20.f) ? v1 : log1pf(__expf(v1));
                v2 = (v2 > 20.f) ? v2 : log1pf(__expf(v2));
                v3 = (v3 > 20.f) ? v3 : log1pf(__expf(v3));
            }
            float2* p0 = (float2*)&Cb[(long)r0 * ldc + col];
            float2* p1 = (float2*)&Cb[(long)r1 * ldc + col];
            if (flags & 4) {
                float2 o0 = *p0, o1 = *p1;
                v0 += o0.x; v1 += o0.y; v2 += o1.x; v3 += o1.y;
            }
            *p0 = make_float2(v0, v1);
            *p1 = make_float2(v2, v3);
        }
    }
}

// ------------------------- transpose ----------------------------------------
__global__ void transpose_kernel(const float* __restrict__ src, float* __restrict__ dst,
                                 int rows, int cols)
{
    __shared__ float tile[32][33];
    int c0 = blockIdx.x * 32, r0 = blockIdx.y * 32, bz = blockIdx.z;
    const float* s = src + (long)bz * rows * cols;
    float* d = dst + (long)bz * rows * cols;
    for (int i = threadIdx.y; i < 32; i += 8)
        tile[i][threadIdx.x] = s[(long)(r0 + i) * cols + c0 + threadIdx.x];
    __syncthreads();
    for (int i = threadIdx.y; i < 32; i += 8)
        d[(long)(c0 + i) * rows + r0 + threadIdx.x] = tile[threadIdx.x][i];
}

// ------------------------- rowmap init --------------------------------------
__global__ void rowmap_init()
{
    int g = blockIdx.x, l = threadIdx.x;
    int k = g & 3, b = g >> 2;
    int s;
    if (k == 0) s = l;
    else if (k == 1) s = swap_l(l);
    else if (k == 2) s = 1023 - l;
    else { int m = 1023 - l; s = swap_l(m); }
    g_rowmap[g * L_LEN + l] = b * L_LEN + s;
}

// ------------------------- patch-expand LN + concat skip --------------------
__global__ void pe_cat_kernel(const float* __restrict__ pe, const float* __restrict__ skip,
                              const float* __restrict__ nw, const float* __restrict__ nb,
                              float* __restrict__ cat)
{
    int pix = blockIdx.x;
    int b = pix >> 10, Y = (pix >> 5) & 31, X = pix & 31;
    int h = Y >> 1, p = Y & 1, w = X >> 1, q = X & 1;
    const float* src = pe + (long)(b * 256 + h * 16 + w) * 1536 + (p * 2 + q) * 384;

    __shared__ float red[32];
    float v[3]; float ssum = 0.f;
#pragma unroll
    for (int j = 0; j < 3; j++) { v[j] = src[threadIdx.x + j * 128]; ssum += v[j]; }
    float mean = block_reduce_sum(ssum, red) * (1.f / 384.f);
    float vs = 0.f;
#pragma unroll
    for (int j = 0; j < 3; j++) { float d = v[j] - mean; vs += d * d; }
    float var = block_reduce_sum(vs, red) * (1.f / 384.f);
    float rstd = rsqrtf(var + 1e-5f);

    float* dst = cat + (long)pix * 768;
#pragma unroll
    for (int j = 0; j < 3; j++) {
        int c = threadIdx.x + j * 128;
        dst[c] = (v[j] - mean) * rstd * nw[c] + nb[c];
    }
    const float* sp = skip + (long)b * 384 * 1024 + (Y * 32 + X);
#pragma unroll
    for (int j = 0; j < 3; j++) {
        int c = threadIdx.x + j * 128;
        dst[384 + c] = sp[(long)c * 1024];
    }
}

// ------------------------- LN over 384 ---------------------------------------
__global__ void ln384_kernel(const float* __restrict__ in, float* __restrict__ out,
                             const float* __restrict__ w, const float* __restrict__ b)
{
    int row = blockIdx.x;
    const float* src = in + (long)row * 384;
    __shared__ float red[32];
    float v[3]; float ssum = 0.f;
#pragma unroll
    for (int j = 0; j < 3; j++) { v[j] = src[threadIdx.x + j * 128]; ssum += v[j]; }
    float mean = block_reduce_sum(ssum, red) * (1.f / 384.f);
    float vs = 0.f;
#pragma unroll
    for (int j = 0; j < 3; j++) { float d = v[j] - mean; vs += d * d; }
    float var = block_reduce_sum(vs, red) * (1.f / 384.f);
    float rstd = rsqrtf(var + 1e-5f);
    float* dst = out + (long)row * 384;
#pragma unroll
    for (int j = 0; j < 3; j++) {
        int c = threadIdx.x + j * 128;
        dst[c] = (v[j] - mean) * rstd * w[c] + b[c];
    }
}

// ------------------------- depthwise 3x3 conv + bias + silu ------------------
__global__ void conv_kernel(const float* __restrict__ xz, const float* __restrict__ cw,
                            const float* __restrict__ cb, float* __restrict__ xc)
{
    int pix = blockIdx.x;
    int b = pix >> 10, Y = (pix >> 5) & 31, X = pix & 31;
    int t = threadIdx.x;
    float acc[3] = {0.f, 0.f, 0.f};
    for (int dy = -1; dy <= 1; dy++) {
        int yy = Y + dy; if ((unsigned)yy >= 32u) continue;
        for (int dx = -1; dx <= 1; dx++) {
            int xx = X + dx; if ((unsigned)xx >= 32u) continue;
            const float* row = xz + (long)(b * 1024 + yy * 32 + xx) * 1536;
            int widx = (dy + 1) * 3 + (dx + 1);
#pragma unroll
            for (int j = 0; j < 3; j++) {
                int c = t + j * 256;
                acc[j] = fmaf(row[c], cw[c * 9 + widx], acc[j]);
            }
        }
    }
    float* dst = xc + (long)pix * 768;
#pragma unroll
    for (int j = 0; j < 3; j++) {
        int c = t + j * 256;
        float v = acc[j] + cb[c];
        dst[c] = silu_f(v);
    }
}

// ------------------------- selective scan -----------------------------------
__global__ void scan_kernel(const float* __restrict__ dts, const float* __restrict__ xc,
                            const float* __restrict__ xdbl, const float* __restrict__ A_log,
                            const float* __restrict__ Ds, float* __restrict__ ys)
{
    int g = blockIdx.x;
    int k = g & 3, b = g >> 2;
    int tid = threadIdx.x;
    int n = tid & 15;
    int d = blockIdx.y * 8 + (tid >> 4);

    float A = -__expf(A_log[((long)(k * DI + d)) * NST + n]);
    float h = 0.f;
    float Dv = Ds[k * DI + d];

    const float* dtp = dts + (long)g * L_LEN * DI + d;
    const float* xdp = xdbl + (long)g * L_LEN * CT;
    const float* xcb = xc + (long)b * L_LEN * DI + d;
    float* yp = ys + (long)g * L_LEN * DI + d;

    for (int l = 0; l < L_LEN; l++) {
        int s;
        if (k == 0) s = l;
        else if (k == 1) s = swap_l(l);
        else if (k == 2) s = 1023 - l;
        else { int m = 1023 - l; s = swap_l(m); }

        float dt = dtp[(long)l * DI];
        float u  = xcb[(long)s * DI];
        const float* bc = xdp + l * CT;
        float Bn = bc[RLOW + n];
        float Cn = bc[RLOW + NST + n];

        float e = __expf(dt * A);
        h = fmaf(e, h, dt * u * Bn);
        float t = h * Cn;
        t += __shfl_xor_sync(0xffffffffu, t, 1);
        t += __shfl_xor_sync(0xffffffffu, t, 2);
        t += __shfl_xor_sync(0xffffffffu, t, 4);
        t += __shfl_xor_sync(0xffffffffu, t, 8);
        if (n == 0) yp[(long)l * DI] = fmaf(Dv, u, t);
    }
}

// ------------------------- combine + out-LN + silu gate ----------------------
__global__ void combine_kernel(const float* __restrict__ ys, const float* __restrict__ xz,
                               const float* __restrict__ onw, const float* __restrict__ onb,
                               float* __restrict__ yout)
{
    int bs = blockIdx.x;
    int b = bs >> 10, s = bs & 1023;
    int sw = swap_l(s);
    long base0 = ((long)(b * 4 + 0) * L_LEN + s)          * DI;
    long base1 = ((long)(b * 4 + 1) * L_LEN + sw)         * DI;
    long base2 = ((long)(b * 4 + 2) * L_LEN + (1023 - s)) * DI;
    long base3 = ((long)(b * 4 + 3) * L_LEN + (1023 - sw))* DI;

    __shared__ float red[32];
    float v[3]; float ssum = 0.f;
#pragma unroll
    for (int j = 0; j < 3; j++) {
        int c = threadIdx.x + j * 256;
        v[j] = ys[base0 + c] + ys[base1 + c] + ys[base2 + c] + ys[base3 + c];
        ssum += v[j];
    }
    float mean = block_reduce_sum(ssum, red) * (1.f / 768.f);
    float vs = 0.f;
#pragma unroll
    for (int j = 0; j < 3; j++) { float d = v[j] - mean; vs += d * d; }
    float var = block_reduce_sum(vs, red) * (1.f / 768.f);
    float rstd = rsqrtf(var + 1e-5f);

#pragma unroll
    for (int j = 0; j < 3; j++) {
        int c = threadIdx.x + j * 256;
        float zz = xz[(long)bs * 1536 + 768 + c];
        yout[(long)bs * DI + c] = ((v[j] - mean) * rstd * onw[c] + onb[c]) * silu_f(zz);
    }
}

// ---------------------------------------------------------------------------
extern "C" void kernel_launch(void* const* d_in, const int* in_sizes, int n_in,
                              void* d_out, int out_size)
{
    const float* x      = (const float*)d_in[0];
    const float* skip   = (const float*)d_in[1];
    const float* pe_w   = (const float*)d_in[2];
    const float* pe_nw  = (const float*)d_in[3];
    const float* pe_nb  = (const float*)d_in[4];
    const float* lp_w   = (const float*)d_in[5];
    const float* lp_b   = (const float*)d_in[6];
    const float* bln_w  = (const float*)d_in[7];
    const float* bln_b  = (const float*)d_in[8];
    const float* in_w   = (const float*)d_in[9];
    const float* conv_w = (const float*)d_in[10];
    const float* conv_b = (const float*)d_in[11];
    const float* xp_w   = (const float*)d_in[12];
    const float* dt_w   = (const float*)d_in[13];
    const float* dt_b   = (const float*)d_in[14];
    const float* A_log  = (const float*)d_in[15];
    const float* Ds     = (const float*)d_in[16];
    const float* on_w   = (const float*)d_in[17];
    const float* on_b   = (const float*)d_in[18];
    const float* out_w  = (const float*)d_in[19];
    float* out = (float*)d_out;

    float *xT, *pe, *cat, *xh, *hbuf, *xz, *xc, *xdbl, *dts, *ys, *ybuf;
    int* rowmap;
    cudaGetSymbolAddress((void**)&xT,   g_xT);
    cudaGetSymbolAddress((void**)&pe,   g_pe);
    cudaGetSymbolAddress((void**)&cat,  g_cat);
    cudaGetSymbolAddress((void**)&xh,   g_xh);
    cudaGetSymbolAddress((void**)&hbuf, g_h);
    cudaGetSymbolAddress((void**)&xz,   g_xz);
    cudaGetSymbolAddress((void**)&xc,   g_xc);
    cudaGetSymbolAddress((void**)&xdbl, g_xdbl);
    cudaGetSymbolAddress((void**)&dts,  g_dts);
    cudaGetSymbolAddress((void**)&ys,   g_ys);
    cudaGetSymbolAddress((void**)&ybuf, g_y);
    cudaGetSymbolAddress((void**)&rowmap, g_rowmap);

    // x (B,768,16,16) -> xT (B,256,768)
    transpose_kernel<<<dim3(256 / 32, 768 / 32, 2), dim3(32, 8)>>>(x, xT, 768, 256);
    rowmap_init<<<8, 1024>>>();

    // patch-expand GEMM: (512 x 1536 x 768)
    gemm_tc<<<dim3(24, 8, 1), 128>>>(xT, pe_w, nullptr, pe, 512, 1536, 768,
                                     768, 768, 1536, 0, 0, 1, 0, 0, nullptr, 0, 0);
    pe_cat_kernel<<<2048, 128>>>(pe, skip, pe_nw, pe_nb, cat);
    // linear proj: (2048 x 384 x 768) + bias
    gemm_tc<<<dim3(6, 32, 1), 128>>>(cat, lp_w, lp_b, xh, 2048, 384, 768,
                                     768, 768, 384, 0, 0, 1, 0, 0, nullptr, 0, 1);

    for (int layer = 0; layer < 2; layer++) {
        ln384_kernel<<<2048, 128>>>(xh, hbuf, bln_w + layer * 384, bln_b + layer * 384);
        // in_proj: (2048 x 1536 x 384)
        gemm_tc<<<dim3(24, 32, 1), 128>>>(hbuf, in_w + (long)layer * 1536 * 384, nullptr, xz,
                                          2048, 1536, 384, 384, 384, 1536,
                                          0, 0, 1, 0, 0, nullptr, 0, 0);
        conv_kernel<<<2048, 256>>>(xz, conv_w + (long)layer * 768 * 9,
                                   conv_b + layer * 768, xc);
        // x_proj: 8 x (1024 x 80 x 768), row-permuted A
        gemm_tc<<<dim3(2, 16, 8), 128>>>(xc, xp_w + (long)layer * 4 * 80 * 768, nullptr, xdbl,
                                         1024, 80, 768, 768, 768, 80,
                                         0, (long)80 * 768, 4, 0, (long)1024 * 80,
                                         rowmap, 1024, 0);
        // dt_proj: 8 x (1024 x 768 x 48) + bias + softplus
        gemm_tc<<<dim3(12, 16, 8), 128>>>(xdbl, dt_w + (long)layer * 4 * 768 * 48,
                                          dt_b + (long)layer * 4 * 768, dts,
                                          1024, 768, 48, 80, 48, 768,
                                          (long)1024 * 80, (long)768 * 48, 4, 768,
                                          (long)1024 * 768, nullptr, 0, 1 | 2);
        scan_kernel<<<dim3(8, 96), 128>>>(dts, xc, xdbl,
                                          A_log + (long)layer * 4 * 768 * 16,
                                          Ds + (long)layer * 4 * 768, ys);
        combine_kernel<<<2048, 256>>>(ys, xz, on_w + layer * 768, on_b + layer * 768, ybuf);
        // out_proj + residual: (2048 x 384 x 768)
        gemm_tc<<<dim3(6, 32, 1), 128>>>(ybuf, out_w + (long)layer * 384 * 768, nullptr, xh,
                                         2048, 384, 768, 768, 768, 384,
                                         0, 0, 1, 0, 0, nullptr, 0, 4);
    }

    transpose_kernel<<<dim3(384 / 32, 1024 / 32, 2), dim3(32, 8)>>>(xh, out, 1024, 384);
}